// round 12
// baseline (speedup 1.0000x reference)
#include <cuda_runtime.h>
#include <cstdint>

#define HH      1024
#define NMODES  64
#define LLEN    2048
#define TPB     128
#define GRID    1024         // 1 head per CTA

// smem (dynamic), per chunk of 32 modes (k=64):
//  Apack: kk(8) x [mt(2) x slot(8) x n3(4)] x 16B = 8 KB
//  Bpack: kk(8) x [w(4) x lane(32)] x 16B        = 16 KB
#define A_BYTES   8192
#define B_BYTES   16384
#define SMEM_BYTES (A_BYTES + B_BYTES)

__device__ __forceinline__ uint32_t tf32c(float f) {
    uint32_t r; asm("cvt.rna.tf32.f32 %0,%1;" : "=r"(r) : "f"(f)); return r;
}
__device__ __forceinline__ uint32_t smem_u32(const void* p) {
    uint32_t a;
    asm("{ .reg .u64 t; cvta.to.shared.u64 t, %1; cvt.u32.u64 %0, t; }" : "=r"(a) : "l"(p));
    return a;
}
__device__ __forceinline__ void sts128(uint32_t a, uint32_t x, uint32_t y, uint32_t z, uint32_t w) {
    asm volatile("st.shared.v4.u32 [%0],{%1,%2,%3,%4};" :: "r"(a), "r"(x), "r"(y), "r"(z), "r"(w) : "memory");
}
__device__ __forceinline__ void lds128(uint32_t a, uint32_t& x, uint32_t& y, uint32_t& z, uint32_t& w) {
    asm volatile("ld.shared.v4.u32 {%0,%1,%2,%3},[%4];" : "=r"(x), "=r"(y), "=r"(z), "=r"(w) : "r"(a));
}
__device__ __forceinline__ void mma8(float* d,
                                     uint32_t a0, uint32_t a1, uint32_t a2, uint32_t a3,
                                     uint32_t b0, uint32_t b1) {
    asm volatile(
        "mma.sync.aligned.m16n8k8.row.col.f32.tf32.tf32.f32 "
        "{%0,%1,%2,%3},{%4,%5,%6,%7},{%8,%9},{%0,%1,%2,%3};"
        : "+f"(d[0]), "+f"(d[1]), "+f"(d[2]), "+f"(d[3])
        : "r"(a0), "r"(a1), "r"(a2), "r"(a3), "r"(b0), "r"(b1));
}
__device__ __forceinline__ void cmul(float& xr, float& xi, float br, float bi) {
    const float t = xr * br - xi * bi;
    xi = xr * bi + xi * br;
    xr = t;
}

__global__ __launch_bounds__(TPB, 7)   // 7 CTAs/SM, 148*7=1036 >= 1024: single wave
void ssd_tc_v12_kernel(
    const float* __restrict__ log_dt,
    const float* __restrict__ log_w_real,
    const float* __restrict__ w_imag,
    const float* __restrict__ C_re,
    const float* __restrict__ C_im,
    float* __restrict__ out)
{
    extern __shared__ __align__(16) char smem_raw[];
    const uint32_t aA = smem_u32(smem_raw);
    const uint32_t aB = aA + A_BYTES;

    const int tid  = threadIdx.x;
    const int lane = tid & 31;
    const int warp = tid >> 5;
    const int m    = tid & 31;     // mode within chunk
    const int q    = tid >> 5;     // 0..3 : gen work split
    const int mt   = q & 1;        // A m-tile
    const int sh   = q >> 1;       // A slot half
    const int r4   = lane >> 2;
    const int c4   = lane & 3;

    const int kkg = m >> 2;        // this mode's k-group (0..7)
    const int n3  = m & 3;
    const uint32_t kxA = (uint32_t)(kkg & 1) << 6;
    const uint32_t kxB = (uint32_t)(kkg & 1) << 6;

    const int h = blockIdx.x;
    const float dt = expf(log_dt[h]);    // per-head, once

    float acc[16];
    #pragma unroll
    for (int i = 0; i < 16; i++) acc[i] = 0.0f;

    #pragma unroll 1
    for (int c = 0; c < 2; c++) {
        const int n = c * 32 + m;

        // ---------- consts for this thread's mode ----------
        const float wr = -__expf(log_w_real[h * NMODES + n]);
        const float wi = w_imag[h * NMODES + n];
        const float ar = wr * dt;
        const float ai = wi * dt;

        float sn, cs;
        const float ez = expf(ar);               // accurate: amplified along chain
        sincosf(ai, &sn, &cs);                   // accurate, small arg
        const float zr = ez * cs, zi = ez * sn;

        // 2*Cmod = 2*C*(z-1)/w
        const float inv = __fdividef(1.0f, wr * wr + wi * wi);
        const float zm  = zr - 1.0f;
        const float tr  = (zm * wr + zi * wi) * inv;
        const float ti  = (zi * wr - zm * wi) * inv;
        const float cre = C_re[h * NMODES + n];
        const float cim = C_im[h * NMODES + n];
        float ur = 2.0f * (cre * tr - cim * ti);
        float ui = 2.0f * (cre * ti + cim * tr);

        // squaring chain z^2 .. z^1024
        float pr = zr, pi = zi;
#define SQ_ { const float t_ = pr * pr - pi * pi; pi = 2.0f * pr * pi; pr = t_; }
        SQ_ SQ_ SQ_                                   // z^8
        const float z8r = pr, z8i = pi;
        SQ_                                           // z^16
        const float z16r = pr, z16i = pi;
        SQ_                                           // z^32
        const float z32r = pr, z32i = pi;
        SQ_                                           // z^64
        const float z64r = pr, z64i = pi;
        SQ_ SQ_                                       // z^256
        const float z256r = pr, z256i = pi;
        SQ_                                           // z^512
        const float z512r = pr, z512i = pi;
        SQ_                                           // z^1024
#undef SQ_
        // ---------- A fragments: rows (16mt + 4sh + t, +8), step x z^64 ----------
        {
            float u1r = ur, u1i = ui;
            if (mt) cmul(u1r, u1i, pr, pi);          // x z^1024
            if (sh) cmul(u1r, u1i, z256r, z256i);    // x z^256
            float u2r = u1r, u2i = u1i;
            cmul(u2r, u2i, z512r, z512i);            // rows +8
            const uint32_t baseA = aA + (uint32_t)kkg * 1024 + (uint32_t)mt * 512 + (uint32_t)n3 * 16;
            #pragma unroll
            for (int t = 0; t < 4; t++) {
                const uint32_t s = (uint32_t)(4 * sh + t);
                sts128(baseA + ((s * 64) ^ kxA),
                       tf32c(u1r), tf32c(u2r), tf32c(u1i), tf32c(u2i));
                cmul(u1r, u1i, z64r, z64i);
                cmul(u2r, u2i, z64r, z64i);
            }
        }

        // ---------- B fragments: lane slot = (j, n3); b = 16q + j and +8 ----------
        // Bpack[kk][w][lane] = {Re(b), -Im(b), Re(b+8), -Im(b+8)}, b = 16w + r4, mode 4kk+c4
        {
            float v0r = 1.0f, v0i = 0.0f;
            if (q & 1) cmul(v0r, v0i, z16r, z16i);
            if (q & 2) cmul(v0r, v0i, z32r, z32i);   // z^(16q)
            float v1r = v0r, v1i = v0i;
            cmul(v1r, v1i, z8r, z8i);                // b + 8
            const uint32_t baseB = aB + (uint32_t)kkg * 2048 + (uint32_t)q * 512 + (uint32_t)n3 * 16;
            #pragma unroll
            for (int j = 0; j < 8; j++) {
                sts128(baseB + (((uint32_t)j * 64) ^ kxB),
                       tf32c(v0r), tf32c(-v0i), tf32c(v1r), tf32c(-v1i));
                cmul(v0r, v0i, zr, zi);
                cmul(v1r, v1i, zr, zi);
            }
        }
        __syncthreads();

        // ---------- GEMM chunk: 8 kk, accumulate; 3 LDS + 4 MMA per kk ----------
        const uint32_t rdA = aA + (uint32_t)lane * 16;
        const uint32_t rdB = aB + (uint32_t)warp * 512 + (uint32_t)lane * 16;

        #pragma unroll
        for (int kk = 0; kk < 8; kk++) {
            const uint32_t sw = (uint32_t)(kk & 1) << 6;

            uint32_t a00, a01, a02, a03, a10, a11, a12, a13;
            lds128((rdA ^ sw) + (uint32_t)kk * 1024,       a00, a01, a02, a03);
            lds128((rdA ^ sw) + (uint32_t)kk * 1024 + 512, a10, a11, a12, a13);

            uint32_t b00, b01, b10, b11;
            lds128((rdB ^ sw) + (uint32_t)kk * 2048, b00, b01, b10, b11);

            mma8(acc + 0,  a00, a01, a02, a03, b00, b01);
            mma8(acc + 4,  a00, a01, a02, a03, b10, b11);
            mma8(acc + 8,  a10, a11, a12, a13, b00, b01);
            mma8(acc + 12, a10, a11, a12, a13, b10, b11);
        }

        if (c == 0) __syncthreads();   // before chunk-1 gen overwrites smem
    }

    // ---------- store (l = 64*a + b) ----------
    float* op = out + (size_t)h * LLEN;
    #pragma unroll
    for (int m2 = 0; m2 < 2; m2++) {
        #pragma unroll
        for (int nt = 0; nt < 2; nt++) {
            const float* a = acc + (m2 * 2 + nt) * 4;
            const int row = 16 * m2 + r4;
            const int col = 16 * warp + 8 * nt + 2 * c4;
            *reinterpret_cast<float2*>(op + row * 64 + col)       = make_float2(a[0], a[1]);
            *reinterpret_cast<float2*>(op + (row + 8) * 64 + col) = make_float2(a[2], a[3]);
        }
    }
}

extern "C" void kernel_launch(void* const* d_in, const int* in_sizes, int n_in,
                              void* d_out, int out_size)
{
    const float* log_dt     = (const float*)d_in[0];
    const float* log_w_real = (const float*)d_in[1];
    const float* w_imag     = (const float*)d_in[2];
    const float* C_re       = (const float*)d_in[3];
    const float* C_im       = (const float*)d_in[4];
    float*       out        = (float*)d_out;

    cudaFuncSetAttribute(ssd_tc_v12_kernel,
                         cudaFuncAttributeMaxDynamicSharedMemorySize, SMEM_BYTES);
    ssd_tc_v12_kernel<<<GRID, TPB, SMEM_BYTES>>>(log_dt, log_w_real, w_imag, C_re, C_im, out);
}

// round 13
// speedup vs baseline: 1.0253x; 1.0253x over previous
#include <cuda_runtime.h>
#include <cstdint>

#define HH      1024
#define NMODES  64
#define LLEN    2048
#define TPB     128
#define GRID    1024         // 1 head per CTA

// smem (dynamic):
//  Apack: kk(8) x [mt(2) x slot(8) x n3(4)] x 16B = 8 KB
//  Bpack: kk(8) x [w(4) x lane(32)] x 16B        = 16 KB
//  SC   : 9 fields x 64 (chunk,mode) x float2    = 4.6 KB
#define A_BYTES   8192
#define B_BYTES   16384
#define SC_BYTES  (9 * 64 * 8)
#define SMEM_BYTES (A_BYTES + B_BYTES + SC_BYTES)

__device__ __forceinline__ uint32_t tf32c(float f) {
    uint32_t r; asm("cvt.rna.tf32.f32 %0,%1;" : "=r"(r) : "f"(f)); return r;
}
__device__ __forceinline__ uint32_t smem_u32(const void* p) {
    uint32_t a;
    asm("{ .reg .u64 t; cvta.to.shared.u64 t, %1; cvt.u32.u64 %0, t; }" : "=r"(a) : "l"(p));
    return a;
}
__device__ __forceinline__ void sts128(uint32_t a, uint32_t x, uint32_t y, uint32_t z, uint32_t w) {
    asm volatile("st.shared.v4.u32 [%0],{%1,%2,%3,%4};" :: "r"(a), "r"(x), "r"(y), "r"(z), "r"(w) : "memory");
}
__device__ __forceinline__ void lds128(uint32_t a, uint32_t& x, uint32_t& y, uint32_t& z, uint32_t& w) {
    asm volatile("ld.shared.v4.u32 {%0,%1,%2,%3},[%4];" : "=r"(x), "=r"(y), "=r"(z), "=r"(w) : "r"(a));
}
__device__ __forceinline__ void mma8(float* d,
                                     uint32_t a0, uint32_t a1, uint32_t a2, uint32_t a3,
                                     uint32_t b0, uint32_t b1) {
    asm volatile(
        "mma.sync.aligned.m16n8k8.row.col.f32.tf32.tf32.f32 "
        "{%0,%1,%2,%3},{%4,%5,%6,%7},{%8,%9},{%0,%1,%2,%3};"
        : "+f"(d[0]), "+f"(d[1]), "+f"(d[2]), "+f"(d[3])
        : "r"(a0), "r"(a1), "r"(a2), "r"(a3), "r"(b0), "r"(b1));
}
__device__ __forceinline__ void cmul(float& xr, float& xi, float br, float bi) {
    const float t = xr * br - xi * bi;
    xi = xr * bi + xi * br;
    xr = t;
}

__global__ __launch_bounds__(TPB, 7)   // 7 CTAs/SM, 148*7=1036 >= 1024: single wave
void ssd_tc_v13_kernel(
    const float* __restrict__ log_dt,
    const float* __restrict__ log_w_real,
    const float* __restrict__ w_imag,
    const float* __restrict__ C_re,
    const float* __restrict__ C_im,
    float* __restrict__ out)
{
    extern __shared__ __align__(16) char smem_raw[];
    const uint32_t aA = smem_u32(smem_raw);
    const uint32_t aB = aA + A_BYTES;
    float2* SC = reinterpret_cast<float2*>(smem_raw + A_BYTES + B_BYTES);  // SC[f*64 + (c<<5|m)]

    const int tid  = threadIdx.x;
    const int lane = tid & 31;
    const int warp = tid >> 5;
    const int m    = tid & 31;     // mode within chunk
    const int q    = tid >> 5;     // 0..3 : gen work split
    const int mt   = q & 1;        // A m-tile
    const int sh   = q >> 1;       // A slot half
    const int r4   = lane >> 2;
    const int c4   = lane & 3;

    const int kkg = m >> 2;        // this mode's k-group (0..7)
    const int n3  = m & 3;
    const uint32_t kx = (uint32_t)(kkg & 1) << 6;

    const int h = blockIdx.x;

    // ---------- Phase 0: consts for all 64 (mode, chunk) pairs, computed ONCE ----------
    if (tid < 64) {
        const int n0 = tid;                       // n = chunk*32 + mode, tid == (c<<5)|m
        const float dt = expf(log_dt[h]);
        const float wr = -__expf(log_w_real[h * NMODES + n0]);
        const float wi = w_imag[h * NMODES + n0];
        const float ar = wr * dt;
        const float ai = wi * dt;

        float sn, cs;
        const float ez = expf(ar);                // accurate: amplified along chain
        sincosf(ai, &sn, &cs);                    // accurate, small arg
        const float zr = ez * cs, zi = ez * sn;

        // 2*Cmod = 2*C*(z-1)/w
        const float inv = __fdividef(1.0f, wr * wr + wi * wi);
        const float zm  = zr - 1.0f;
        const float tr  = (zm * wr + zi * wi) * inv;
        const float ti  = (zi * wr - zm * wi) * inv;
        const float cre = C_re[h * NMODES + n0];
        const float cim = C_im[h * NMODES + n0];
        const float ur = 2.0f * (cre * tr - cim * ti);
        const float ui = 2.0f * (cre * ti + cim * tr);

        float pr = zr, pi = zi;
        SC[0 * 64 + tid] = make_float2(zr, zi);
#define SQ_ { const float t_ = pr * pr - pi * pi; pi = 2.0f * pr * pi; pr = t_; }
        SQ_ SQ_ SQ_  SC[1 * 64 + tid] = make_float2(pr, pi);   // z^8
        SQ_          SC[2 * 64 + tid] = make_float2(pr, pi);   // z^16
        SQ_          SC[3 * 64 + tid] = make_float2(pr, pi);   // z^32
        SQ_          SC[4 * 64 + tid] = make_float2(pr, pi);   // z^64
        SQ_ SQ_      SC[5 * 64 + tid] = make_float2(pr, pi);   // z^256
        SQ_          SC[6 * 64 + tid] = make_float2(pr, pi);   // z^512
        SQ_          SC[7 * 64 + tid] = make_float2(pr, pi);   // z^1024
#undef SQ_
        SC[8 * 64 + tid] = make_float2(ur, ui);
    }
    __syncthreads();

    float acc[16];
    #pragma unroll
    for (int i = 0; i < 16; i++) acc[i] = 0.0f;

    #pragma unroll 1
    for (int c = 0; c < 2; c++) {
        const int idx = (c << 5) | m;
        const float2 Z    = SC[0 * 64 + idx];
        const float2 Z64  = SC[4 * 64 + idx];
        const float2 Z512 = SC[6 * 64 + idx];

        // ---------- A fragments: rows (16mt + 4sh + t, +8), step x z^64 ----------
        {
            const float2 U = SC[8 * 64 + idx];
            float u1r = U.x, u1i = U.y;
            if (mt) { const float2 Z1k  = SC[7 * 64 + idx]; cmul(u1r, u1i, Z1k.x,  Z1k.y);  }
            if (sh) { const float2 Z256 = SC[5 * 64 + idx]; cmul(u1r, u1i, Z256.x, Z256.y); }
            float u2r = u1r, u2i = u1i;
            cmul(u2r, u2i, Z512.x, Z512.y);          // rows +8
            const uint32_t baseA = aA + (uint32_t)kkg * 1024 + (uint32_t)mt * 512 + (uint32_t)n3 * 16;
            #pragma unroll
            for (int t = 0; t < 4; t++) {
                const uint32_t s = (uint32_t)(4 * sh + t);
                sts128(baseA + ((s * 64) ^ kx),
                       tf32c(u1r), tf32c(u2r), tf32c(u1i), tf32c(u2i));
                cmul(u1r, u1i, Z64.x, Z64.y);
                cmul(u2r, u2i, Z64.x, Z64.y);
            }
        }

        // ---------- B fragments: Bpack[kk][w][lane] = {b, -bi, b+8, -(b+8)i}, b = 16q + j ----------
        {
            float v0r = 1.0f, v0i = 0.0f;
            if (q & 1) { const float2 Z16 = SC[2 * 64 + idx]; cmul(v0r, v0i, Z16.x, Z16.y); }
            if (q & 2) { const float2 Z32 = SC[3 * 64 + idx]; cmul(v0r, v0i, Z32.x, Z32.y); }
            float v1r = v0r, v1i = v0i;
            { const float2 Z8 = SC[1 * 64 + idx]; cmul(v1r, v1i, Z8.x, Z8.y); }   // b + 8
            const uint32_t baseB = aB + (uint32_t)kkg * 2048 + (uint32_t)q * 512 + (uint32_t)n3 * 16;
            #pragma unroll
            for (int j = 0; j < 8; j++) {
                sts128(baseB + (((uint32_t)j * 64) ^ kx),
                       tf32c(v0r), tf32c(-v0i), tf32c(v1r), tf32c(-v1i));
                cmul(v0r, v0i, Z.x, Z.y);
                cmul(v1r, v1i, Z.x, Z.y);
            }
        }
        __syncthreads();

        // ---------- GEMM chunk: 8 kk, accumulate; 3 LDS + 4 MMA per kk ----------
        const uint32_t rdA = aA + (uint32_t)lane * 16;
        const uint32_t rdB = aB + (uint32_t)warp * 512 + (uint32_t)lane * 16;

        #pragma unroll
        for (int kk = 0; kk < 8; kk++) {
            const uint32_t sw = (uint32_t)(kk & 1) << 6;

            uint32_t a00, a01, a02, a03, a10, a11, a12, a13;
            lds128((rdA ^ sw) + (uint32_t)kk * 1024,       a00, a01, a02, a03);
            lds128((rdA ^ sw) + (uint32_t)kk * 1024 + 512, a10, a11, a12, a13);

            uint32_t b00, b01, b10, b11;
            lds128((rdB ^ sw) + (uint32_t)kk * 2048, b00, b01, b10, b11);

            mma8(acc + 0,  a00, a01, a02, a03, b00, b01);
            mma8(acc + 4,  a00, a01, a02, a03, b10, b11);
            mma8(acc + 8,  a10, a11, a12, a13, b00, b01);
            mma8(acc + 12, a10, a11, a12, a13, b10, b11);
        }

        if (c == 0) __syncthreads();   // before chunk-1 gen overwrites smem
    }

    // ---------- store (l = 64*a + b) ----------
    float* op = out + (size_t)h * LLEN;
    #pragma unroll
    for (int m2 = 0; m2 < 2; m2++) {
        #pragma unroll
        for (int nt = 0; nt < 2; nt++) {
            const float* a = acc + (m2 * 2 + nt) * 4;
            const int row = 16 * m2 + r4;
            const int col = 16 * warp + 8 * nt + 2 * c4;
            *reinterpret_cast<float2*>(op + row * 64 + col)       = make_float2(a[0], a[1]);
            *reinterpret_cast<float2*>(op + (row + 8) * 64 + col) = make_float2(a[2], a[3]);
        }
    }
}

extern "C" void kernel_launch(void* const* d_in, const int* in_sizes, int n_in,
                              void* d_out, int out_size)
{
    const float* log_dt     = (const float*)d_in[0];
    const float* log_w_real = (const float*)d_in[1];
    const float* w_imag     = (const float*)d_in[2];
    const float* C_re       = (const float*)d_in[3];
    const float* C_im       = (const float*)d_in[4];
    float*       out        = (float*)d_out;

    cudaFuncSetAttribute(ssd_tc_v13_kernel,
                         cudaFuncAttributeMaxDynamicSharedMemorySize, SMEM_BYTES);
    ssd_tc_v13_kernel<<<GRID, TPB, SMEM_BYTES>>>(log_dt, log_w_real, w_imag, C_re, C_im, out);
}

// round 14
// speedup vs baseline: 1.0547x; 1.0286x over previous
#include <cuda_runtime.h>
#include <cstdint>

#define HH      1024
#define NMODES  64
#define LLEN    2048
#define TPB     128
#define GRID    1024         // 1 head per CTA

// smem (dynamic):
//  Apack: kk(8) x [mt(2) x slot(8) x n3(4)] x 16B = 8 KB
//  Bpack: kk(8) x [w(4) x lane(32)] x 16B        = 16 KB
//  SC   : 10 fields x 64 (chunk,mode) x float2   = 5 KB
#define A_BYTES   8192
#define B_BYTES   16384
#define SC_BYTES  (10 * 64 * 8)
#define SMEM_BYTES (A_BYTES + B_BYTES + SC_BYTES)

__device__ __forceinline__ uint32_t smem_u32(const void* p) {
    uint32_t a;
    asm("{ .reg .u64 t; cvta.to.shared.u64 t, %1; cvt.u32.u64 %0, t; }" : "=r"(a) : "l"(p));
    return a;
}
__device__ __forceinline__ void sts128f(uint32_t a, float x, float y, float z, float w) {
    asm volatile("st.shared.v4.b32 [%0],{%1,%2,%3,%4};" :: "r"(a), "f"(x), "f"(y), "f"(z), "f"(w) : "memory");
}
__device__ __forceinline__ void lds128(uint32_t a, uint32_t& x, uint32_t& y, uint32_t& z, uint32_t& w) {
    asm volatile("ld.shared.v4.u32 {%0,%1,%2,%3},[%4];" : "=r"(x), "=r"(y), "=r"(z), "=r"(w) : "r"(a));
}
__device__ __forceinline__ void mma8(float* d,
                                     uint32_t a0, uint32_t a1, uint32_t a2, uint32_t a3,
                                     uint32_t b0, uint32_t b1) {
    asm volatile(
        "mma.sync.aligned.m16n8k8.row.col.f32.tf32.tf32.f32 "
        "{%0,%1,%2,%3},{%4,%5,%6,%7},{%8,%9},{%0,%1,%2,%3};"
        : "+f"(d[0]), "+f"(d[1]), "+f"(d[2]), "+f"(d[3])
        : "r"(a0), "r"(a1), "r"(a2), "r"(a3), "r"(b0), "r"(b1));
}
__device__ __forceinline__ void cmul(float& xr, float& xi, float br, float bi) {
    const float t = xr * br - xi * bi;
    xi = xr * bi + xi * br;
    xr = t;
}

__global__ __launch_bounds__(TPB, 7)   // 7 CTAs/SM, 148*7=1036 >= 1024: single wave
void ssd_tc_v14_kernel(
    const float* __restrict__ log_dt,
    const float* __restrict__ log_w_real,
    const float* __restrict__ w_imag,
    const float* __restrict__ C_re,
    const float* __restrict__ C_im,
    float* __restrict__ out)
{
    extern __shared__ __align__(16) char smem_raw[];
    const uint32_t aA = smem_u32(smem_raw);
    const uint32_t aB = aA + A_BYTES;
    float2* SC = reinterpret_cast<float2*>(smem_raw + A_BYTES + B_BYTES);  // SC[f*64 + (c<<5|m)]

    const int tid  = threadIdx.x;
    const int lane = tid & 31;
    const int warp = tid >> 5;
    const int m    = tid & 31;     // mode within chunk
    const int q    = tid >> 5;     // 0..3 : gen work split
    const int mt   = q & 1;        // A m-tile
    const int sh   = q >> 1;       // A slot half
    const int r4   = lane >> 2;
    const int c4   = lane & 3;

    const int kkg = m >> 2;        // this mode's k-group (0..7)
    const int n3  = m & 3;
    const uint32_t kx = (uint32_t)(kkg & 1) << 6;

    const int h = blockIdx.x;

    // ---------- Phase 0: consts for all 64 (mode, chunk) pairs, computed ONCE ----------
    if (tid < 64) {
        const int n0 = tid;                       // n = chunk*32 + mode, tid == (c<<5)|m
        const float dt = expf(log_dt[h]);
        const float wr = -__expf(log_w_real[h * NMODES + n0]);
        const float wi = w_imag[h * NMODES + n0];
        const float ar = wr * dt;
        const float ai = wi * dt;

        float sn, cs;
        const float ez = expf(ar);                // accurate: amplified along chain
        sincosf(ai, &sn, &cs);                    // accurate, small arg
        const float zr = ez * cs, zi = ez * sn;

        // 2*Cmod = 2*C*(z-1)/w, bias-corrected for tf32 truncation:
        // A side scaled by (1+2^-10) so trunc(A)*trunc(B) is unbiased.
        const float inv = __fdividef(1.0f, wr * wr + wi * wi);
        const float zm  = zr - 1.0f;
        const float tr  = (zm * wr + zi * wi) * inv;
        const float ti  = (zi * wr - zm * wi) * inv;
        const float cre = C_re[h * NMODES + n0];
        const float cim = C_im[h * NMODES + n0];
        const float corr = 2.0f * (1.0f + 0.0009765625f);   // 2 * (1 + 2^-10)
        const float ur = corr * (cre * tr - cim * ti);
        const float ui = corr * (cre * ti + cim * tr);

        float pr = zr, pi = zi;
        SC[0 * 64 + tid] = make_float2(zr, zi);
#define SQ_ { const float t_ = pr * pr - pi * pi; pi = 2.0f * pr * pi; pr = t_; }
        SQ_ SQ_      SC[1 * 64 + tid] = make_float2(pr, pi);   // z^4
        SQ_          SC[2 * 64 + tid] = make_float2(pr, pi);   // z^8
        SQ_          SC[3 * 64 + tid] = make_float2(pr, pi);   // z^16
        SQ_          SC[4 * 64 + tid] = make_float2(pr, pi);   // z^32
        SQ_          SC[5 * 64 + tid] = make_float2(pr, pi);   // z^64
        SQ_ SQ_      SC[6 * 64 + tid] = make_float2(pr, pi);   // z^256
        SQ_          SC[7 * 64 + tid] = make_float2(pr, pi);   // z^512
        SQ_          SC[8 * 64 + tid] = make_float2(pr, pi);   // z^1024
#undef SQ_
        SC[9 * 64 + tid] = make_float2(ur, ui);
    }
    __syncthreads();

    float acc[16];
    #pragma unroll
    for (int i = 0; i < 16; i++) acc[i] = 0.0f;

    #pragma unroll 1
    for (int c = 0; c < 2; c++) {
        const int idx = (c << 5) | m;
        const float2 Z = SC[0 * 64 + idx];

        // ---------- A fragments: rows (16mt + 4sh + t, +8), step x z^64 ----------
        {
            const float2 Z64  = SC[5 * 64 + idx];
            const float2 Z512 = SC[7 * 64 + idx];
            const float2 U    = SC[9 * 64 + idx];
            float u1r = U.x, u1i = U.y;
            if (mt) { const float2 Z1k  = SC[8 * 64 + idx]; cmul(u1r, u1i, Z1k.x,  Z1k.y);  }
            if (sh) { const float2 Z256 = SC[6 * 64 + idx]; cmul(u1r, u1i, Z256.x, Z256.y); }
            float u2r = u1r, u2i = u1i;
            cmul(u2r, u2i, Z512.x, Z512.y);          // rows +8
            const uint32_t baseA = aA + (uint32_t)kkg * 1024 + (uint32_t)mt * 512 + (uint32_t)n3 * 16;
            #pragma unroll
            for (int t = 0; t < 4; t++) {
                const uint32_t s = (uint32_t)(4 * sh + t);
                sts128f(baseA + ((s * 64) ^ kx), u1r, u2r, u1i, u2i);
                cmul(u1r, u1i, Z64.x, Z64.y);
                cmul(u2r, u2i, Z64.x, Z64.y);
            }
        }

        // ---------- B fragments: quad chains b = 16q + {j, j+4, j+8, j+12} ----------
        // Bpack[kk][w][lane] = {Re(b), -Im(b), Re(b+8), -Im(b+8)}, b = 16w + r4, mode 4kk+c4
        {
            const float2 Z4 = SC[1 * 64 + idx];
            const float2 Z8 = SC[2 * 64 + idx];
            float a0r = 1.0f, a0i = 0.0f;
            if (q & 1) { const float2 Z16 = SC[3 * 64 + idx]; cmul(a0r, a0i, Z16.x, Z16.y); }
            if (q & 2) { const float2 Z32 = SC[4 * 64 + idx]; cmul(a0r, a0i, Z32.x, Z32.y); }
            float a1r = a0r, a1i = a0i; cmul(a1r, a1i, Z4.x, Z4.y);   // b+4
            float b0r = a0r, b0i = a0i; cmul(b0r, b0i, Z8.x, Z8.y);   // b+8
            float b1r = a1r, b1i = a1i; cmul(b1r, b1i, Z8.x, Z8.y);   // b+12
            const uint32_t baseB = aB + (uint32_t)kkg * 2048 + (uint32_t)q * 512 + (uint32_t)n3 * 16;
            #pragma unroll
            for (int j = 0; j < 4; j++) {
                sts128f(baseB + (((uint32_t)j * 64) ^ kx),       a0r, -a0i, b0r, -b0i);
                sts128f(baseB + (((uint32_t)(j + 4) * 64) ^ kx), a1r, -a1i, b1r, -b1i);
                cmul(a0r, a0i, Z.x, Z.y);
                cmul(a1r, a1i, Z.x, Z.y);
                cmul(b0r, b0i, Z.x, Z.y);
                cmul(b1r, b1i, Z.x, Z.y);
            }
        }
        __syncthreads();

        // ---------- GEMM chunk: 8 kk, accumulate; 3 LDS + 4 MMA per kk ----------
        const uint32_t rdA = aA + (uint32_t)lane * 16;
        const uint32_t rdB = aB + (uint32_t)warp * 512 + (uint32_t)lane * 16;

        #pragma unroll
        for (int kk = 0; kk < 8; kk++) {
            const uint32_t sw = (uint32_t)(kk & 1) << 6;

            uint32_t a00, a01, a02, a03, a10, a11, a12, a13;
            lds128((rdA ^ sw) + (uint32_t)kk * 1024,       a00, a01, a02, a03);
            lds128((rdA ^ sw) + (uint32_t)kk * 1024 + 512, a10, a11, a12, a13);

            uint32_t b00, b01, b10, b11;
            lds128((rdB ^ sw) + (uint32_t)kk * 2048, b00, b01, b10, b11);

            mma8(acc + 0,  a00, a01, a02, a03, b00, b01);
            mma8(acc + 4,  a00, a01, a02, a03, b10, b11);
            mma8(acc + 8,  a10, a11, a12, a13, b00, b01);
            mma8(acc + 12, a10, a11, a12, a13, b10, b11);
        }

        if (c == 0) __syncthreads();   // before chunk-1 gen overwrites smem
    }

    // ---------- store (l = 64*a + b) ----------
    float* op = out + (size_t)h * LLEN;
    #pragma unroll
    for (int m2 = 0; m2 < 2; m2++) {
        #pragma unroll
        for (int nt = 0; nt < 2; nt++) {
            const float* a = acc + (m2 * 2 + nt) * 4;
            const int row = 16 * m2 + r4;
            const int col = 16 * warp + 8 * nt + 2 * c4;
            *reinterpret_cast<float2*>(op + row * 64 + col)       = make_float2(a[0], a[1]);
            *reinterpret_cast<float2*>(op + (row + 8) * 64 + col) = make_float2(a[2], a[3]);
        }
    }
}

extern "C" void kernel_launch(void* const* d_in, const int* in_sizes, int n_in,
                              void* d_out, int out_size)
{
    const float* log_dt     = (const float*)d_in[0];
    const float* log_w_real = (const float*)d_in[1];
    const float* w_imag     = (const float*)d_in[2];
    const float* C_re       = (const float*)d_in[3];
    const float* C_im       = (const float*)d_in[4];
    float*       out        = (float*)d_out;

    cudaFuncSetAttribute(ssd_tc_v14_kernel,
                         cudaFuncAttributeMaxDynamicSharedMemorySize, SMEM_BYTES);
    ssd_tc_v14_kernel<<<GRID, TPB, SMEM_BYTES>>>(log_dt, log_w_real, w_imag, C_re, C_im, out);
}